// round 16
// baseline (speedup 1.0000x reference)
#include <cuda_runtime.h>
#include <cuda_fp16.h>
#include <cstdint>

#define F   128
#define NG  512
#define MAXN 100000
#define CAP 96
#define GB  304     // GEMM persistent blocks

// ---- scratch (static device globals: allocation-free, zero-initialized at load) ----
__device__ __half g_A[(size_t)MAXN * F];    // GEMM1 output, UNSCALED (fp16)
__device__ float  g_z[MAXN];                // z[d] = h'[d] . v
__device__ int    g_adj[(size_t)MAXN * CAP];
__device__ int    g_indeg[MAXN];
__device__ float  g_poolsc[NG];
__device__ float  g_cnt[NG];
__device__ float  g_v[F];                   // v = W2 @ Wl
__device__ float  g_c0[1];                  // b2.Wl + bl

// ============================ GEMM helpers ============================
#define XS_STRIDE 132
#define TROWS 32
#define XBUF (TROWS * XS_STRIDE)
#define SMEM_GEMM (2 * XBUF * 4)     // double buffer: 33792 B

__device__ __forceinline__ uint32_t f2tf32(float v) {
    uint32_t u;
    asm("cvt.rna.tf32.f32 %0, %1;" : "=r"(u) : "f"(v));
    return u;
}
__device__ __forceinline__ uint32_t smem_u32(const void* p) {
    uint32_t a;
    asm("{ .reg .u64 t; cvta.to.shared.u64 t, %1; cvt.u32.u64 %0, t; }" : "=r"(a) : "l"(p));
    return a;
}
__device__ __forceinline__ void cp16(uint32_t dst, const void* src) {
    asm volatile("cp.async.ca.shared.global [%0], [%1], 16;" :: "r"(dst), "l"(src));
}
__device__ __forceinline__ void prefetch_tile(const float* X, uint32_t xs_base, int buf,
                                              int tile, int ntiles, int M, int tid) {
    if (tile < ntiles) {
        int row0 = tile * TROWS;
        for (int g = tid; g < TROWS * 32; g += 256) {
            int r = g >> 5, c4 = g & 31;
            uint32_t dst = xs_base + (uint32_t)(((buf * XBUF) + r * XS_STRIDE + c4 * 4) * 4);
            if (row0 + r < M)
                cp16(dst, (const float4*)X + (size_t)(row0 + r) * 32 + c4);
            else
                asm volatile("st.shared.v4.b32 [%0], {%1,%1,%1,%1};" :: "r"(dst), "r"(0));
        }
    }
    asm volatile("cp.async.commit_group;");
}

// ============================ mega kernel ============================
// blocks [0, GB):            persistent tf32 GEMM, UNSCALED fp16 out (depends only on x, W1)
// blocks [GB, GB+129):       v = W2@Wl reduction (+ c0)
// blocks [GB+129, ...):      edge scatter (adjacency build) + per-graph node counts
__global__ void __launch_bounds__(256, 2) k_mega(
    const float* __restrict__ X, const float* __restrict__ W1g,
    __half* __restrict__ Y, int M, int ntiles,
    const int* __restrict__ src, const int* __restrict__ dst, int E,
    const int* __restrict__ batch,
    const float* __restrict__ W2, const float* __restrict__ Wl,
    const float* __restrict__ b2, const float* __restrict__ bl)
{
    int tid = threadIdx.x;

    if (blockIdx.x >= GB) {
        int b = blockIdx.x - GB;
        if (b < F + 1) {
            __shared__ float sh[256];
            const float* row = (b < F) ? (W2 + (size_t)b * F) : b2;
            sh[tid] = (tid < F) ? row[tid] * Wl[tid] : 0.f;
            __syncthreads();
            for (int o = 128; o > 0; o >>= 1) {
                if (tid < o) sh[tid] += sh[tid + o];
                __syncthreads();
            }
            if (tid == 0) {
                if (b < F) g_v[b] = sh[0];
                else       g_c0[0] = sh[0] + bl[0];
            }
            return;
        }
        int i = (b - (F + 1)) * blockDim.x + tid;
        if (i < E) {
            int d = dst[i];
            int slot = atomicAdd(&g_indeg[d], 1);
            if (slot < CAP) g_adj[(size_t)d * CAP + slot] = src[i];
        }
        if (i < M) atomicAdd(&g_cnt[batch[i]], 1.0f);
        return;
    }

    // ---- GEMM persistent block ----
    extern __shared__ float sm[];
    int wid = tid >> 5, lane = tid & 31;
    int gr = lane >> 2, tg = lane & 3;
    int col0 = wid * 16;
    uint32_t xs_base = smem_u32(sm);

    float2 breg[16][2];
    #pragma unroll
    for (int ks = 0; ks < 16; ++ks)
        #pragma unroll
        for (int j = 0; j < 2; ++j) {
            int col = col0 + j * 8 + gr;
            breg[ks][j].x = __uint_as_float(f2tf32(W1g[(ks * 8 + tg) * 128 + col]));
            breg[ks][j].y = __uint_as_float(f2tf32(W1g[(ks * 8 + 4 + tg) * 128 + col]));
        }

    prefetch_tile(X, xs_base, 0, blockIdx.x, ntiles, M, tid);

    int p = 0;
    for (int t = blockIdx.x; t < ntiles; t += GB, p ^= 1) {
        prefetch_tile(X, xs_base, p ^ 1, t + GB, ntiles, M, tid);
        asm volatile("cp.async.wait_group 1;");
        __syncthreads();

        const float* Xs = sm + p * XBUF;
        float c[2][2][4];
        #pragma unroll
        for (int a = 0; a < 2; ++a)
            #pragma unroll
            for (int b2i = 0; b2i < 2; ++b2i)
                #pragma unroll
                for (int k = 0; k < 4; ++k) c[a][b2i][k] = 0.f;

        const float* xa = Xs + gr * XS_STRIDE + tg;
        #pragma unroll
        for (int ks = 0; ks < 16; ++ks) {
            int k0 = ks * 8;
            uint32_t a0 = __float_as_uint(xa[k0]);
            uint32_t a1 = __float_as_uint(xa[8 * XS_STRIDE + k0]);
            uint32_t a2 = __float_as_uint(xa[k0 + 4]);
            uint32_t a3 = __float_as_uint(xa[8 * XS_STRIDE + k0 + 4]);
            uint32_t a4 = __float_as_uint(xa[16 * XS_STRIDE + k0]);
            uint32_t a5 = __float_as_uint(xa[24 * XS_STRIDE + k0]);
            uint32_t a6 = __float_as_uint(xa[16 * XS_STRIDE + k0 + 4]);
            uint32_t a7 = __float_as_uint(xa[24 * XS_STRIDE + k0 + 4]);
            #pragma unroll
            for (int j = 0; j < 2; ++j) {
                uint32_t b0 = __float_as_uint(breg[ks][j].x);
                uint32_t b1 = __float_as_uint(breg[ks][j].y);
                asm volatile(
                    "mma.sync.aligned.m16n8k8.row.col.f32.tf32.tf32.f32 "
                    "{%0,%1,%2,%3}, {%4,%5,%6,%7}, {%8,%9}, {%0,%1,%2,%3};"
                    : "+f"(c[0][j][0]), "+f"(c[0][j][1]), "+f"(c[0][j][2]), "+f"(c[0][j][3])
                    : "r"(a0), "r"(a1), "r"(a2), "r"(a3), "r"(b0), "r"(b1));
                asm volatile(
                    "mma.sync.aligned.m16n8k8.row.col.f32.tf32.tf32.f32 "
                    "{%0,%1,%2,%3}, {%4,%5,%6,%7}, {%8,%9}, {%0,%1,%2,%3};"
                    : "+f"(c[1][j][0]), "+f"(c[1][j][1]), "+f"(c[1][j][2]), "+f"(c[1][j][3])
                    : "r"(a4), "r"(a5), "r"(a6), "r"(a7), "r"(b0), "r"(b1));
            }
        }

        // epilogue: UNSCALED fp16 stores (no dependency on g_indeg)
        int row0 = t * TROWS;
        #pragma unroll
        for (int r2 = 0; r2 < 2; ++r2) {
            int r_top = row0 + r2 * 16 + gr;
            int r_bot = r_top + 8;
            #pragma unroll
            for (int j = 0; j < 2; ++j) {
                int col = col0 + j * 8 + tg * 2;
                if (r_top < M)
                    *(__half2*)(Y + (size_t)r_top * 128 + col) =
                        __float22half2_rn(make_float2(c[r2][j][0], c[r2][j][1]));
                if (r_bot < M)
                    *(__half2*)(Y + (size_t)r_bot * 128 + col) =
                        __float22half2_rn(make_float2(c[r2][j][2], c[r2][j][3]));
            }
        }
        __syncthreads();
    }
}

// ============================ layer-1 aggregation -> scalar z ============================
__device__ __forceinline__ uint2 ld_row(const __half* H, int s, int lane) {
    return ((const uint2*)(H + (size_t)s * F))[lane];
}
#define H2REF(u) (*reinterpret_cast<__half2*>(&(u)))

__device__ __forceinline__ float dinv_node(int s) {
    return rsqrtf((float)g_indeg[s] + 1.0f);
}

// scaled 4-row half2 fma-tree accumulate
__device__ __forceinline__ void add_group4s(float4& acc,
                                            uint2 u0, uint2 u1, uint2 u2, uint2 u3,
                                            __half2 h0, __half2 h1, __half2 h2, __half2 h3) {
    __half2 ax = __hmul2(H2REF(u0.x), h0);
    ax = __hfma2(H2REF(u1.x), h1, ax);
    ax = __hfma2(H2REF(u2.x), h2, ax);
    ax = __hfma2(H2REF(u3.x), h3, ax);
    __half2 ay = __hmul2(H2REF(u0.y), h0);
    ay = __hfma2(H2REF(u1.y), h1, ay);
    ay = __hfma2(H2REF(u2.y), h2, ay);
    ay = __hfma2(H2REF(u3.y), h3, ay);
    float2 fx = __half22float2(ax);
    float2 fy = __half22float2(ay);
    acc.x += fx.x; acc.y += fx.y;
    acc.z += fy.x; acc.w += fy.y;
}

// z[d] = ( dinv[d] * relu(dinv[d]*(sum dinv[s]H[s] + dinv[d]H[d]) + b1) ) . v
__global__ void k_agg1(const __half* __restrict__ H, const float* __restrict__ b1, int n) {
    int w = (blockIdx.x * blockDim.x + threadIdx.x) >> 5;
    int lane = threadIdx.x & 31;
    if (w >= n) return;
    int d = w;
    int cnt = g_indeg[d];
    float dd = rsqrtf((float)cnt + 1.0f);
    if (cnt > CAP) cnt = CAP;

    // self row in fp32
    float4 acc;
    {
        uint2 us = ld_row(H, d, lane);
        float2 a = __half22float2(H2REF(us.x));
        float2 b = __half22float2(H2REF(us.y));
        acc = make_float4(a.x * dd, a.y * dd, b.x * dd, b.y * dd);
    }

    const int* adj = g_adj + (size_t)d * CAP;
    int e = 0;
    for (; e + 8 <= cnt; e += 8) {
        int4 q0 = *(const int4*)(adj + e);
        int4 q1 = *(const int4*)(adj + e + 4);
        uint2 u0 = ld_row(H, q0.x, lane);
        uint2 u1 = ld_row(H, q0.y, lane);
        uint2 u2 = ld_row(H, q0.z, lane);
        uint2 u3 = ld_row(H, q0.w, lane);
        uint2 u4 = ld_row(H, q1.x, lane);
        uint2 u5 = ld_row(H, q1.y, lane);
        uint2 u6 = ld_row(H, q1.z, lane);
        uint2 u7 = ld_row(H, q1.w, lane);
        __half2 h0 = __float2half2_rn(dinv_node(q0.x));
        __half2 h1 = __float2half2_rn(dinv_node(q0.y));
        __half2 h2 = __float2half2_rn(dinv_node(q0.z));
        __half2 h3 = __float2half2_rn(dinv_node(q0.w));
        __half2 h4 = __float2half2_rn(dinv_node(q1.x));
        __half2 h5 = __float2half2_rn(dinv_node(q1.y));
        __half2 h6 = __float2half2_rn(dinv_node(q1.z));
        __half2 h7 = __float2half2_rn(dinv_node(q1.w));
        add_group4s(acc, u0, u1, u2, u3, h0, h1, h2, h3);
        add_group4s(acc, u4, u5, u6, u7, h4, h5, h6, h7);
    }
    if (e + 4 <= cnt) {
        int4 q = *(const int4*)(adj + e);
        uint2 u0 = ld_row(H, q.x, lane);
        uint2 u1 = ld_row(H, q.y, lane);
        uint2 u2 = ld_row(H, q.z, lane);
        uint2 u3 = ld_row(H, q.w, lane);
        __half2 h0 = __float2half2_rn(dinv_node(q.x));
        __half2 h1 = __float2half2_rn(dinv_node(q.y));
        __half2 h2 = __float2half2_rn(dinv_node(q.z));
        __half2 h3 = __float2half2_rn(dinv_node(q.w));
        add_group4s(acc, u0, u1, u2, u3, h0, h1, h2, h3);
        e += 4;
    }
    for (; e < cnt; ++e) {
        int s = adj[e];
        float r = dinv_node(s);
        uint2 u = ld_row(H, s, lane);
        float2 a = __half22float2(H2REF(u.x));
        float2 b = __half22float2(H2REF(u.y));
        acc.x += a.x * r; acc.y += a.y * r;
        acc.z += b.x * r; acc.w += b.y * r;
    }

    float4 bv = ((const float4*)b1)[lane];
    float4 vv = ((const float4*)g_v)[lane];
    float hx = fmaxf(acc.x * dd + bv.x, 0.f) * dd;
    float hy = fmaxf(acc.y * dd + bv.y, 0.f) * dd;
    float hz = fmaxf(acc.z * dd + bv.z, 0.f) * dd;
    float hw = fmaxf(acc.w * dd + bv.w, 0.f) * dd;
    float partial = hx * vv.x + hy * vv.y + hz * vv.z + hw * vv.w;
    #pragma unroll
    for (int o = 16; o > 0; o >>= 1)
        partial += __shfl_xor_sync(0xffffffffu, partial, o);
    if (lane == 0) g_z[d] = partial;
}

// ============================ layer-2 scalar aggregation + pool ============================
__global__ void k_agg2(const int* __restrict__ batch, int n) {
    int d = blockIdx.x * blockDim.x + threadIdx.x;
    if (d >= n) return;
    int cnt = g_indeg[d];
    float dd = rsqrtf((float)cnt + 1.0f);
    if (cnt > CAP) cnt = CAP;
    float s = g_z[d];
    const int* adj = g_adj + (size_t)d * CAP;
    int e = 0;
    for (; e + 4 <= cnt; e += 4) {
        int4 q = *(const int4*)(adj + e);
        s += g_z[q.x] + g_z[q.y] + g_z[q.z] + g_z[q.w];
    }
    for (; e < cnt; ++e) s += g_z[adj[e]];
    atomicAdd(&g_poolsc[batch[d]], dd * s);
}

// ============================ head + cleanup for next replay ============================
// Globals are zero-initialized at module load, so the first call sees clean state;
// this kernel restores that invariant at the end of every launch (graph replay safe).
__global__ void k_final(float* __restrict__ out, int n) {
    int i = blockIdx.x * blockDim.x + threadIdx.x;
    if (i < NG) {
        out[i] = g_poolsc[i] / fmaxf(g_cnt[i], 1.0f) + g_c0[0];
        g_poolsc[i] = 0.f;
        g_cnt[i] = 0.f;
    }
    if (i < n) g_indeg[i] = 0;
}

// ============================ launcher ============================
extern "C" void kernel_launch(void* const* d_in, const int* in_sizes, int n_in,
                              void* d_out, int out_size) {
    const float* x     = (const float*)d_in[0];
    const int*   ei    = (const int*)d_in[1];
    const int*   batch = (const int*)d_in[3];
    const float* W1 = (const float*)d_in[4];
    const float* b1 = (const float*)d_in[5];
    const float* W2 = (const float*)d_in[6];
    const float* b2 = (const float*)d_in[7];
    const float* Wl = (const float*)d_in[8];
    const float* bl = (const float*)d_in[9];

    int n = in_sizes[0] / F;
    int E = in_sizes[1] / 2;
    const int* src = ei;
    const int* dst = ei + E;

    cudaFuncSetAttribute(k_mega, cudaFuncAttributeMaxDynamicSharedMemorySize, SMEM_GEMM);

    void* pA;
    cudaGetSymbolAddress(&pA, g_A);
    __half* A = (__half*)pA;

    const int T = 256;
    int ntiles = (n + TROWS - 1) / TROWS;
    int work = (E > n) ? E : n;
    unsigned mega_blocks = (unsigned)(GB + (F + 1) + (work + T - 1) / T);

    // GEMM + v-prep + adjacency build, all overlapped in one launch
    k_mega<<<mega_blocks, T, SMEM_GEMM>>>(x, W1, A, n, ntiles,
                                          src, dst, E, batch, W2, Wl, b2, bl);

    long long aggthr = (long long)n * 32;
    unsigned aggblk = (unsigned)((aggthr + T - 1) / T);

    // layer 1: aggregation (dinv applied inline) -> scalar z
    k_agg1<<<aggblk, T>>>(A, b1, n);

    // layer 2: scalar aggregation + pooled mean
    k_agg2<<<(n + T - 1) / T, T>>>(batch, n);

    // head + state cleanup for next replay
    k_final<<<(n + T - 1) / T, T>>>((float*)d_out, n);
}

// round 17
// speedup vs baseline: 1.2574x; 1.2574x over previous
#include <cuda_runtime.h>
#include <cuda_fp16.h>
#include <cstdint>

#define F   128
#define NG  512
#define MAXN 100000
#define CAP 96

// ---- scratch (static device globals: allocation-free) ----
__device__ __half g_A[(size_t)MAXN * F];    // GEMM1 output, dinv-scaled (fp16)
__device__ float  g_z[MAXN];                // z[d] = h'[d] . v
__device__ int    g_adj[(size_t)MAXN * CAP];
__device__ int    g_indeg[MAXN];
__device__ float  g_poolsc[NG];             // scalar pool accumulator
__device__ float  g_cnt[NG];
__device__ float  g_v[F];                   // v = W2 @ Wl
__device__ float  g_c0[1];                  // b2.Wl + bl

__device__ __forceinline__ float dinv_of(int node) {
    return rsqrtf((float)g_indeg[node] + 1.0f);
}

// ============================ setup kernels ============================
__global__ void k_init(int n) {
    int i = blockIdx.x * blockDim.x + threadIdx.x;
    if (i < n)  g_indeg[i] = 0;
    if (i < NG) { g_poolsc[i] = 0.0f; g_cnt[i] = 0.0f; }
}

// blocks 0..128: v/c0 reduction (block j<128 -> g_v[j], block 128 -> c0).
// blocks >=129: edge scatter + per-graph node counts.
__global__ void k_scatter(const int* __restrict__ src, const int* __restrict__ dst,
                          int E, const int* __restrict__ batch, int n,
                          const float* __restrict__ W2, const float* __restrict__ Wl,
                          const float* __restrict__ b2, const float* __restrict__ bl) {
    int b = blockIdx.x;
    if (b < F + 1) {
        __shared__ float sh[256];
        int t = threadIdx.x;
        const float* row = (b < F) ? (W2 + (size_t)b * F) : b2;
        sh[t] = (t < F) ? row[t] * Wl[t] : 0.f;
        __syncthreads();
        for (int o = 128; o > 0; o >>= 1) {
            if (t < o) sh[t] += sh[t + o];
            __syncthreads();
        }
        if (t == 0) {
            if (b < F) g_v[b] = sh[0];
            else       g_c0[0] = sh[0] + bl[0];
        }
        return;
    }
    int i = (b - (F + 1)) * blockDim.x + threadIdx.x;
    if (i < E) {
        int d = dst[i];
        int slot = atomicAdd(&g_indeg[d], 1);
        if (slot < CAP) g_adj[(size_t)d * CAP + slot] = src[i];
    }
    if (i < n) atomicAdd(&g_cnt[batch[i]], 1.0f);
}

// ============================ persistent tf32 GEMM, W in regs, dinv-scaled fp16 out ============
#define XS_STRIDE 132
#define TROWS 32
#define XBUF (TROWS * XS_STRIDE)
#define SMEM_GEMM (3 * XBUF * 4)

__device__ __forceinline__ uint32_t f2tf32(float v) {
    uint32_t u;
    asm("cvt.rna.tf32.f32 %0, %1;" : "=r"(u) : "f"(v));
    return u;
}
__device__ __forceinline__ uint32_t smem_u32(const void* p) {
    uint32_t a;
    asm("{ .reg .u64 t; cvta.to.shared.u64 t, %1; cvt.u32.u64 %0, t; }" : "=r"(a) : "l"(p));
    return a;
}
__device__ __forceinline__ void cp16(uint32_t dst, const void* src) {
    asm volatile("cp.async.ca.shared.global [%0], [%1], 16;" :: "r"(dst), "l"(src));
}
__device__ __forceinline__ void prefetch_tile(const float* X, uint32_t xs_base, int buf,
                                              int tile, int ntiles, int M, int tid) {
    if (tile < ntiles) {
        int row0 = tile * TROWS;
        for (int g = tid; g < TROWS * 32; g += 256) {
            int r = g >> 5, c4 = g & 31;
            uint32_t dst = xs_base + (uint32_t)(((buf * XBUF) + r * XS_STRIDE + c4 * 4) * 4);
            if (row0 + r < M)
                cp16(dst, (const float4*)X + (size_t)(row0 + r) * 32 + c4);
            else
                asm volatile("st.shared.v4.b32 [%0], {%1,%1,%1,%1};" :: "r"(dst), "r"(0));
        }
    }
    asm volatile("cp.async.commit_group;");
}

__global__ void __launch_bounds__(256, 2) k_gemm_tc(const float* __restrict__ X,
                                                    const float* __restrict__ W,
                                                    __half* __restrict__ Y,
                                                    int M, int ntiles) {
    extern __shared__ float sm[];
    int tid = threadIdx.x, wid = tid >> 5, lane = tid & 31;
    int gr = lane >> 2;
    int tg = lane & 3;
    int col0 = wid * 16;
    uint32_t xs_base = smem_u32(sm);
    int G = gridDim.x;

    float2 breg[16][2];
    #pragma unroll
    for (int ks = 0; ks < 16; ++ks)
        #pragma unroll
        for (int j = 0; j < 2; ++j) {
            int col = col0 + j * 8 + gr;
            breg[ks][j].x = __uint_as_float(f2tf32(W[(ks * 8 + tg) * 128 + col]));
            breg[ks][j].y = __uint_as_float(f2tf32(W[(ks * 8 + 4 + tg) * 128 + col]));
        }

    prefetch_tile(X, xs_base, 0, blockIdx.x, ntiles, M, tid);
    prefetch_tile(X, xs_base, 1, blockIdx.x + G, ntiles, M, tid);

    int i = 0;
    for (int t = blockIdx.x; t < ntiles; t += G, ++i) {
        int p = i % 3;
        prefetch_tile(X, xs_base, (p + 2) % 3, t + 2 * G, ntiles, M, tid);
        asm volatile("cp.async.wait_group 2;");
        __syncthreads();

        const float* Xs = sm + p * XBUF;
        float c[2][2][4];
        #pragma unroll
        for (int a = 0; a < 2; ++a)
            #pragma unroll
            for (int b = 0; b < 2; ++b)
                #pragma unroll
                for (int k = 0; k < 4; ++k) c[a][b][k] = 0.f;

        const float* xa = Xs + gr * XS_STRIDE + tg;
        #pragma unroll
        for (int ks = 0; ks < 16; ++ks) {
            int k0 = ks * 8;
            uint32_t a0 = __float_as_uint(xa[k0]);
            uint32_t a1 = __float_as_uint(xa[8 * XS_STRIDE + k0]);
            uint32_t a2 = __float_as_uint(xa[k0 + 4]);
            uint32_t a3 = __float_as_uint(xa[8 * XS_STRIDE + k0 + 4]);
            uint32_t a4 = __float_as_uint(xa[16 * XS_STRIDE + k0]);
            uint32_t a5 = __float_as_uint(xa[24 * XS_STRIDE + k0]);
            uint32_t a6 = __float_as_uint(xa[16 * XS_STRIDE + k0 + 4]);
            uint32_t a7 = __float_as_uint(xa[24 * XS_STRIDE + k0 + 4]);
            #pragma unroll
            for (int j = 0; j < 2; ++j) {
                uint32_t b0 = __float_as_uint(breg[ks][j].x);
                uint32_t b1 = __float_as_uint(breg[ks][j].y);
                asm volatile(
                    "mma.sync.aligned.m16n8k8.row.col.f32.tf32.tf32.f32 "
                    "{%0,%1,%2,%3}, {%4,%5,%6,%7}, {%8,%9}, {%0,%1,%2,%3};"
                    : "+f"(c[0][j][0]), "+f"(c[0][j][1]), "+f"(c[0][j][2]), "+f"(c[0][j][3])
                    : "r"(a0), "r"(a1), "r"(a2), "r"(a3), "r"(b0), "r"(b1));
                asm volatile(
                    "mma.sync.aligned.m16n8k8.row.col.f32.tf32.tf32.f32 "
                    "{%0,%1,%2,%3}, {%4,%5,%6,%7}, {%8,%9}, {%0,%1,%2,%3};"
                    : "+f"(c[1][j][0]), "+f"(c[1][j][1]), "+f"(c[1][j][2]), "+f"(c[1][j][3])
                    : "r"(a4), "r"(a5), "r"(a6), "r"(a7), "r"(b0), "r"(b1));
            }
        }

        int row0 = t * TROWS;
        #pragma unroll
        for (int r2 = 0; r2 < 2; ++r2) {
            int r_top = row0 + r2 * 16 + gr;
            int r_bot = r_top + 8;
            float s_top = (r_top < M) ? dinv_of(r_top) : 0.f;
            float s_bot = (r_bot < M) ? dinv_of(r_bot) : 0.f;
            #pragma unroll
            for (int j = 0; j < 2; ++j) {
                int col = col0 + j * 8 + tg * 2;
                if (r_top < M)
                    *(__half2*)(Y + (size_t)r_top * 128 + col) =
                        __float22half2_rn(make_float2(c[r2][j][0] * s_top, c[r2][j][1] * s_top));
                if (r_bot < M)
                    *(__half2*)(Y + (size_t)r_bot * 128 + col) =
                        __float22half2_rn(make_float2(c[r2][j][2] * s_bot, c[r2][j][3] * s_bot));
            }
        }
        __syncthreads();
    }
}

// ============================ layer-1 aggregation -> scalar z ============================
__device__ __forceinline__ uint2 ld_row(const __half* H, int s, int lane) {
    return ((const uint2*)(H + (size_t)s * F))[lane];
}
__device__ __forceinline__ void add_f32(float4& acc, uint2 u) {
    float2 f01 = __half22float2(*reinterpret_cast<__half2*>(&u.x));
    float2 f23 = __half22float2(*reinterpret_cast<__half2*>(&u.y));
    acc.x += f01.x; acc.y += f01.y;
    acc.z += f23.x; acc.w += f23.y;
}
// tree-add 4 rows in half2, flush to fp32 accumulator
__device__ __forceinline__ void add_group4(float4& acc, uint2 u0, uint2 u1, uint2 u2, uint2 u3) {
    __half2 s01 = __hadd2(__hadd2(*reinterpret_cast<__half2*>(&u0.x),
                                  *reinterpret_cast<__half2*>(&u1.x)),
                          __hadd2(*reinterpret_cast<__half2*>(&u2.x),
                                  *reinterpret_cast<__half2*>(&u3.x)));
    __half2 s23 = __hadd2(__hadd2(*reinterpret_cast<__half2*>(&u0.y),
                                  *reinterpret_cast<__half2*>(&u1.y)),
                          __hadd2(*reinterpret_cast<__half2*>(&u2.y),
                                  *reinterpret_cast<__half2*>(&u3.y)));
    float2 f01 = __half22float2(s01);
    float2 f23 = __half22float2(s23);
    acc.x += f01.x; acc.y += f01.y;
    acc.z += f23.x; acc.w += f23.y;
}

// z[d] = ( dinv[d] * relu(dinv[d]*S + b1) ) . v  — h' never stored
__global__ void k_agg1(const __half* __restrict__ H, const float* __restrict__ b1, int n) {
    int w = (blockIdx.x * blockDim.x + threadIdx.x) >> 5;
    int lane = threadIdx.x & 31;
    if (w >= n) return;
    int d = w;
    int cnt = g_indeg[d];
    float dd = rsqrtf((float)cnt + 1.0f);
    if (cnt > CAP) cnt = CAP;

    float4 acc = make_float4(0.f, 0.f, 0.f, 0.f);
    add_f32(acc, ld_row(H, d, lane));     // self loop (rows pre-scaled by dinv)

    const int* adj = g_adj + (size_t)d * CAP;
    int e = 0;
    for (; e + 8 <= cnt; e += 8) {
        int4 q0 = *(const int4*)(adj + e);
        int4 q1 = *(const int4*)(adj + e + 4);
        uint2 u0 = ld_row(H, q0.x, lane);
        uint2 u1 = ld_row(H, q0.y, lane);
        uint2 u2 = ld_row(H, q0.z, lane);
        uint2 u3 = ld_row(H, q0.w, lane);
        uint2 u4 = ld_row(H, q1.x, lane);
        uint2 u5 = ld_row(H, q1.y, lane);
        uint2 u6 = ld_row(H, q1.z, lane);
        uint2 u7 = ld_row(H, q1.w, lane);
        add_group4(acc, u0, u1, u2, u3);
        add_group4(acc, u4, u5, u6, u7);
    }
    if (e + 4 <= cnt) {
        int4 q = *(const int4*)(adj + e);
        uint2 u0 = ld_row(H, q.x, lane);
        uint2 u1 = ld_row(H, q.y, lane);
        uint2 u2 = ld_row(H, q.z, lane);
        uint2 u3 = ld_row(H, q.w, lane);
        add_group4(acc, u0, u1, u2, u3);
        e += 4;
    }
    for (; e < cnt; ++e) add_f32(acc, ld_row(H, adj[e], lane));

    float4 bv = ((const float4*)b1)[lane];
    float4 vv = ((const float4*)g_v)[lane];
    float hx = fmaxf(acc.x * dd + bv.x, 0.f) * dd;
    float hy = fmaxf(acc.y * dd + bv.y, 0.f) * dd;
    float hz = fmaxf(acc.z * dd + bv.z, 0.f) * dd;
    float hw = fmaxf(acc.w * dd + bv.w, 0.f) * dd;
    float partial = hx * vv.x + hy * vv.y + hz * vv.z + hw * vv.w;
    #pragma unroll
    for (int o = 16; o > 0; o >>= 1)
        partial += __shfl_xor_sync(0xffffffffu, partial, o);
    if (lane == 0) g_z[d] = partial;
}

// ============================ layer-2 scalar aggregation + pool ============================
__global__ void k_agg2(const int* __restrict__ batch, int n) {
    int d = blockIdx.x * blockDim.x + threadIdx.x;
    if (d >= n) return;
    int cnt = g_indeg[d];
    float dd = rsqrtf((float)cnt + 1.0f);
    if (cnt > CAP) cnt = CAP;
    float s = g_z[d];
    const int* adj = g_adj + (size_t)d * CAP;
    int e = 0;
    for (; e + 4 <= cnt; e += 4) {
        int4 q = *(const int4*)(adj + e);
        s += g_z[q.x] + g_z[q.y] + g_z[q.z] + g_z[q.w];
    }
    for (; e < cnt; ++e) s += g_z[adj[e]];
    atomicAdd(&g_poolsc[batch[d]], dd * s);
}

// out[g] = poolsc[g]/max(cnt,1) + c0
__global__ void k_final(float* __restrict__ out) {
    int g = blockIdx.x * blockDim.x + threadIdx.x;
    if (g < NG)
        out[g] = g_poolsc[g] / fmaxf(g_cnt[g], 1.0f) + g_c0[0];
}

// ============================ launcher ============================
extern "C" void kernel_launch(void* const* d_in, const int* in_sizes, int n_in,
                              void* d_out, int out_size) {
    const float* x     = (const float*)d_in[0];
    const int*   ei    = (const int*)d_in[1];
    const int*   batch = (const int*)d_in[3];
    const float* W1 = (const float*)d_in[4];
    const float* b1 = (const float*)d_in[5];
    const float* W2 = (const float*)d_in[6];
    const float* b2 = (const float*)d_in[7];
    const float* Wl = (const float*)d_in[8];
    const float* bl = (const float*)d_in[9];

    int n = in_sizes[0] / F;
    int E = in_sizes[1] / 2;
    const int* src = ei;
    const int* dst = ei + E;

    cudaFuncSetAttribute(k_gemm_tc, cudaFuncAttributeMaxDynamicSharedMemorySize, SMEM_GEMM);

    void* pA;
    cudaGetSymbolAddress(&pA, g_A);
    __half* A = (__half*)pA;

    const int T = 256;
    int ntiles = (n + TROWS - 1) / TROWS;
    int gblocks = 304;
    if (gblocks > ntiles) gblocks = ntiles;

    int work = (E > n) ? E : n;
    unsigned scat_blocks = (unsigned)(F + 1 + (work + T - 1) / T);

    k_init<<<(n + T - 1) / T, T>>>(n);
    k_scatter<<<scat_blocks, T>>>(src, dst, E, batch, n, W2, Wl, b2, bl);

    long long aggthr = (long long)n * 32;
    unsigned aggblk = (unsigned)((aggthr + T - 1) / T);

    // layer 1: GEMM (dinv-scaled fp16) -> agg1 (bias+relu+dinv, dot with v -> scalar z)
    k_gemm_tc<<<gblocks, T, SMEM_GEMM>>>(x, W1, A, n, ntiles);
    k_agg1<<<aggblk, T>>>(A, b1, n);

    // layer 2: scalar aggregation + pooled mean + head constant
    k_agg2<<<(n + T - 1) / T, T>>>(batch, n);
    k_final<<<(NG + T - 1) / T, T>>>((float*)d_out);
}